// round 11
// baseline (speedup 1.0000x reference)
#include <cuda_runtime.h>
#include <cuda_fp16.h>

#define NN 8192
#define FF 128
#define PP 16
#define EMAX 262144

// u16[i] = fp16 concat(alpha_row[i]*nf_i, (gamma_row[i]/F)*diff_i)  (512B/row)
// v16[i] = fp16 concat(nf_i, diff_i)                                 (512B/row)
// act-edge value = dot(u16[src], v16[dst]), fp32 accumulate
__device__ __half g_u[NN * 2 * FF];
__device__ __half g_v[NN * 2 * FF];
__device__ float  g_nbeta[NN];     // -beta_row
__device__ float  g_val[EMAX];     // per-act-edge values

static __device__ __forceinline__ unsigned h2_bits(__half2 h) {
    return *reinterpret_cast<unsigned*>(&h);
}

// Zero-fill split point: K1 zeroes [0, S1) floats, K2 zeroes [S1, total)
#define S1_FLOATS (8u * 1024u * 1024u)   // 32 MB

static __device__ __forceinline__ void prep_row(
        int row, int lane,
        const float* __restrict__ feature,
        const float* __restrict__ next_feature,
        const float* __restrict__ persona_t,
        const float* __restrict__ alpha,
        const float* __restrict__ beta,
        const float* __restrict__ gamma) {
    const float4* nf4 = (const float4*)(next_feature + (size_t)row * FF);
    const float4* f4  = (const float4*)(feature      + (size_t)row * FF);
    float4 nf = nf4[lane];
    float4 f  = f4[lane];
    float4 d  = make_float4(f.x - nf.x, f.y - nf.y, f.z - nf.z, f.w - nf.w);

    float ss = nf.x*nf.x + nf.y*nf.y + nf.z*nf.z + nf.w*nf.w;
    #pragma unroll
    for (int o = 16; o; o >>= 1) ss += __shfl_xor_sync(0xffffffffu, ss, o);
    float inv = rsqrtf(ss);
    nf.x *= inv; nf.y *= inv; nf.z *= inv; nf.w *= inv;
    float s2 = nf.x*nf.x + nf.y*nf.y + nf.z*nf.z + nf.w*nf.w;
    #pragma unroll
    for (int o = 16; o; o >>= 1) s2 += __shfl_xor_sync(0xffffffffu, s2, o);
    float inv2 = rsqrtf(s2);
    nf.x *= inv2; nf.y *= inv2; nf.z *= inv2; nf.w *= inv2;

    float pa = 0.f, pb = 0.f, pg = 0.f;
    if (lane < PP) {
        float p = persona_t[(size_t)row * PP + lane];
        pa = p * alpha[lane];
        pb = p * beta[lane];
        pg = p * gamma[lane];
    }
    #pragma unroll
    for (int o = 16; o; o >>= 1) {
        pa += __shfl_xor_sync(0xffffffffu, pa, o);
        pb += __shfl_xor_sync(0xffffffffu, pb, o);
        pg += __shfl_xor_sync(0xffffffffu, pg, o);
    }
    if (lane == 0) g_nbeta[row] = -pb;
    float gg = pg * (1.0f / FF);

    size_t base = (size_t)row * 2 * FF;
    uint2* urow = (uint2*)(g_u + base);
    urow[lane]      = make_uint2(h2_bits(__floats2half2_rn(pa * nf.x, pa * nf.y)),
                                 h2_bits(__floats2half2_rn(pa * nf.z, pa * nf.w)));
    urow[32 + lane] = make_uint2(h2_bits(__floats2half2_rn(gg * d.x, gg * d.y)),
                                 h2_bits(__floats2half2_rn(gg * d.z, gg * d.w)));
    uint2* vrow = (uint2*)(g_v + base);
    vrow[lane]      = make_uint2(h2_bits(__floats2half2_rn(nf.x, nf.y)),
                                 h2_bits(__floats2half2_rn(nf.z, nf.w)));
    vrow[32 + lane] = make_uint2(h2_bits(__floats2half2_rn(d.x, d.y)),
                                 h2_bits(__floats2half2_rn(d.z, d.w)));
}

static __device__ __forceinline__ float edge_dot(int src, int dst, int lane) {
    const uint4* u = (const uint4*)(g_u + (size_t)src * 2 * FF);
    const uint4* v = (const uint4*)(g_v + (size_t)dst * 2 * FF);
    uint4 up = u[lane];
    uint4 vp = v[lane];
    float2 a0 = __half22float2(*(__half2*)&up.x);
    float2 a1 = __half22float2(*(__half2*)&up.y);
    float2 a2 = __half22float2(*(__half2*)&up.z);
    float2 a3 = __half22float2(*(__half2*)&up.w);
    float2 b0 = __half22float2(*(__half2*)&vp.x);
    float2 b1 = __half22float2(*(__half2*)&vp.y);
    float2 b2 = __half22float2(*(__half2*)&vp.z);
    float2 b3 = __half22float2(*(__half2*)&vp.w);
    float s;
    s = a0.x * b0.x;
    s = fmaf(a0.y, b0.y, s);
    s = fmaf(a1.x, b1.x, s);
    s = fmaf(a1.y, b1.y, s);
    s = fmaf(a2.x, b2.x, s);
    s = fmaf(a2.y, b2.y, s);
    s = fmaf(a3.x, b3.x, s);
    s = fmaf(a3.y, b3.y, s);
    return s;
}

// -------- K1: blocks [0,256) prep rows; blocks [256,1024) zero out[0, S1) --------
#define K1_PREP_BLOCKS 256
#define K1_BLOCKS 1024
__global__ void k1_prep_zero(const float* __restrict__ feature,
                             const float* __restrict__ next_feature,
                             const float* __restrict__ persona_t,
                             const float* __restrict__ alpha,
                             const float* __restrict__ beta,
                             const float* __restrict__ gamma,
                             float* __restrict__ out, long total) {
    int bid = blockIdx.x;
    int lane = threadIdx.x & 31;
    if (bid < K1_PREP_BLOCKS) {
        int warp = bid * (blockDim.x >> 5) + (threadIdx.x >> 5);  // 0..2047
        for (int row = warp; row < NN; row += K1_PREP_BLOCKS * 8)
            prep_row(row, lane, feature, next_feature, persona_t, alpha, beta, gamma);
    } else {
        long zt = (long)(bid - K1_PREP_BLOCKS) * blockDim.x + threadIdx.x;
        long zn = (long)(K1_BLOCKS - K1_PREP_BLOCKS) * blockDim.x;
        float4 z = make_float4(0.f, 0.f, 0.f, 0.f);
        float4* o4 = (float4*)out;
        long end4 = (long)S1_FLOATS >> 2;   // S1 is 16B-aligned
        if (end4 > (total >> 2)) end4 = total >> 2;
        for (long i = zt; i < end4; i += zn) o4[i] = z;
    }
}

// -------- K2: even blocks zero out[S1, total); odd blocks compute edge dots --------
#define K2_BLOCKS 2048
__global__ void k2_zero_dots(const int* __restrict__ act_src,
                             const int* __restrict__ act_dst,
                             float* __restrict__ out, long total, int E) {
    int bid = blockIdx.x;
    int lane = threadIdx.x & 31;
    if ((bid & 1) == 0) {
        // zero role: 1024 blocks cover [S1, total)
        long zt = (long)(bid >> 1) * blockDim.x + threadIdx.x;
        long zn = (long)(K2_BLOCKS >> 1) * blockDim.x;
        float4 z = make_float4(0.f, 0.f, 0.f, 0.f);
        float4* o4 = (float4*)out;
        long n4 = total >> 2;
        for (long i = ((long)S1_FLOATS >> 2) + zt; i < n4; i += zn) o4[i] = z;
        for (long i = (n4 << 2) + zt; i < total; i += zn) out[i] = 0.f;
    } else {
        // dot role: 1024 blocks x 8 warps, grid-stride over edges, 2-way unrolled
        int warp = (bid >> 1) * (blockDim.x >> 5) + (threadIdx.x >> 5);  // 0..8191
        const int WN = (K2_BLOCKS >> 1) * 8;                              // 8192
        int e = warp;
        for (; e + WN < E; e += 2 * WN) {
            int s0 = __ldg(&act_src[e]);
            int d0 = __ldg(&act_dst[e]);
            int s1 = __ldg(&act_src[e + WN]);
            int d1 = __ldg(&act_dst[e + WN]);
            float r0 = edge_dot(s0, d0, lane);
            float r1 = edge_dot(s1, d1, lane);
            #pragma unroll
            for (int o = 16; o; o >>= 1) {
                r0 += __shfl_xor_sync(0xffffffffu, r0, o);
                r1 += __shfl_xor_sync(0xffffffffu, r1, o);
            }
            if (lane == 0) { g_val[e] = r0; g_val[e + WN] = r1; }
        }
        for (; e < E; e += WN) {
            int s0 = __ldg(&act_src[e]);
            int d0 = __ldg(&act_dst[e]);
            float r0 = edge_dot(s0, d0, lane);
            #pragma unroll
            for (int o = 16; o; o >>= 1) r0 += __shfl_xor_sync(0xffffffffu, r0, o);
            if (lane == 0) g_val[e] = r0;
        }
    }
}

// -------- K3: scatter atomics (act values + cost) --------
__global__ void scatter_kernel(const int* __restrict__ act_src,
                               const int* __restrict__ act_dst,
                               const int* __restrict__ edge_src,
                               const int* __restrict__ edge_dst,
                               float* __restrict__ out, int E, int Ec) {
    int t = blockIdx.x * blockDim.x + threadIdx.x;
    if (t < E) {
        int src = __ldg(&act_src[t]);
        int dst = __ldg(&act_dst[t]);
        atomicAdd(&out[(size_t)src * NN + dst], g_val[t]);
    } else if (t < E + Ec) {
        int e = t - E;
        int src = __ldg(&edge_src[e]);
        int dst = __ldg(&edge_dst[e]);
        atomicAdd(&out[(size_t)src * NN + dst], g_nbeta[src]);
    }
}

extern "C" void kernel_launch(void* const* d_in, const int* in_sizes, int n_in,
                              void* d_out, int out_size) {
    const float* feature      = (const float*)d_in[0];
    const float* next_feature = (const float*)d_in[1];
    const float* persona_t    = (const float*)d_in[2];
    const float* alpha        = (const float*)d_in[3];
    const float* beta         = (const float*)d_in[4];
    const float* gamma        = (const float*)d_in[5];
    const int*   act_src      = (const int*)d_in[6];
    const int*   act_dst      = (const int*)d_in[7];
    const int*   edge_src     = (const int*)d_in[8];
    const int*   edge_dst     = (const int*)d_in[9];
    float* out = (float*)d_out;
    int E  = in_sizes[6];
    int Ec = in_sizes[8];

    k1_prep_zero<<<K1_BLOCKS, 256>>>(feature, next_feature, persona_t,
                                     alpha, beta, gamma, out, (long)out_size);
    k2_zero_dots<<<K2_BLOCKS, 256>>>(act_src, act_dst, out, (long)out_size, E);
    int st = E + Ec;
    scatter_kernel<<<(st + 255) / 256, 256>>>(act_src, act_dst, edge_src, edge_dst,
                                              out, E, Ec);
}